// round 1
// baseline (speedup 1.0000x reference)
#include <cuda_runtime.h>
#include <math.h>

#define BATCH 512
#define LATENT 256
#define HID 1024
#define OUTD 128
#define SEQ 96
#define G4 4096       // 4*HID
#define KC1 1152      // OUTD+HID  (gemm1 K)
#define KC2 2048      // HID+HID   (gemm2 K)

// ---------------- device scratch (static, no runtime allocation) ----------------
__device__ float g_A1[BATCH * KC1];        // [ x(t) | h1 ]
__device__ float g_A2[BATCH * KC2];        // [ h1   | h2 ]
__device__ float g_C1[BATCH * HID];
__device__ float g_C2[BATCH * HID];
__device__ float g_H2[BATCH * HID];        // fresh h2 (gemm3 input)
__device__ float g_P [BATCH * HID];        // p1 output / gelu buffer
__device__ float g_H0[BATCH * 2 * HID];    // init pre-LN
__device__ float g_W1[(long)G4 * KC1];     // reordered [w_ih0|w_hh0], gate-interleaved rows
__device__ float g_W2[(long)G4 * KC2];     // reordered [w_ih1|w_hh1]
__device__ float g_B1[G4];
__device__ float g_B2[G4];

__device__ __forceinline__ float sigf(float x) { return 1.0f / (1.0f + __expf(-x)); }
__device__ __forceinline__ float geluf(float x) {
    return 0.5f * x * (1.0f + erff(x * 0.70710678118654752f));
}

// ---------------- weight reorder: row (4j+g) <- original row (g*HID + j) ----------------
__global__ void prep_weights(const float* __restrict__ w_ih0, const float* __restrict__ w_hh0,
                             const float* __restrict__ b0,
                             const float* __restrict__ w_ih1, const float* __restrict__ w_hh1,
                             const float* __restrict__ b1) {
    long stride = (long)gridDim.x * blockDim.x;
    long i0 = (long)blockIdx.x * blockDim.x + threadIdx.x;

    for (long idx = i0; idx < (long)G4 * KC1; idx += stride) {
        int r = (int)(idx / KC1), k = (int)(idx % KC1);
        int j = r >> 2, g = r & 3;
        int sr = g * HID + j;
        g_W1[idx] = (k < OUTD) ? w_ih0[(long)sr * OUTD + k]
                               : w_hh0[(long)sr * HID + (k - OUTD)];
    }
    for (long idx = i0; idx < (long)G4 * KC2; idx += stride) {
        int r = (int)(idx / KC2), k = (int)(idx % KC2);
        int j = r >> 2, g = r & 3;
        int sr = g * HID + j;
        g_W2[idx] = (k < HID) ? w_ih1[(long)sr * HID + k]
                              : w_hh1[(long)sr * HID + (k - HID)];
    }
    for (long idx = i0; idx < G4; idx += stride) {
        int j = (int)(idx >> 2), g = (int)(idx & 3);
        g_B1[idx] = b0[g * HID + j];
        g_B2[idx] = b1[g * HID + j];
    }
}

// ---------------- big GEMM: 128x128 tile, K step 16, 256 threads, 8x8/thread ----------------
// C[m,n] = sum_k A[m,k] * W[n,k]   (W row-major [N,K])
// MODE 0: out[m*ldo+n] = C + bias[n]
// MODE 1: LSTM epilogue (interleaved gate quadruples along n)
template <int MODE>
__global__ void __launch_bounds__(256) gemm128(
    const float* __restrict__ A, int lda, int K,
    const float* __restrict__ W,
    const float* __restrict__ bias,
    float* __restrict__ out, int ldo,
    float* __restrict__ cst,
    float* __restrict__ hdst, int ldh, int hoff)
{
    __shared__ float As[16][132];
    __shared__ float Bs[16][132];

    const int tid = threadIdx.x;
    const int tx = tid & 15, ty = tid >> 4;
    const int m0 = blockIdx.x * 128, n0 = blockIdx.y * 128;

    float acc[8][8];
#pragma unroll
    for (int i = 0; i < 8; i++)
#pragma unroll
        for (int j = 0; j < 8; j++) acc[i][j] = 0.0f;

    const float* Ag = A + (long)m0 * lda;
    const float* Wg = W + (long)n0 * K;

    for (int k0 = 0; k0 < K; k0 += 16) {
#pragma unroll
        for (int i = 0; i < 2; i++) {
            int v = tid + i * 256;
            int r = v >> 2, kq = (v & 3) * 4;
            float4 fa = *(const float4*)(Ag + (long)r * lda + k0 + kq);
            As[kq + 0][r] = fa.x; As[kq + 1][r] = fa.y;
            As[kq + 2][r] = fa.z; As[kq + 3][r] = fa.w;
            float4 fb = *(const float4*)(Wg + (long)r * K + k0 + kq);
            Bs[kq + 0][r] = fb.x; Bs[kq + 1][r] = fb.y;
            Bs[kq + 2][r] = fb.z; Bs[kq + 3][r] = fb.w;
        }
        __syncthreads();
#pragma unroll
        for (int k = 0; k < 16; k++) {
            float ra[8], rb[8];
            *(float4*)(ra)     = *(const float4*)&As[k][ty * 4];
            *(float4*)(ra + 4) = *(const float4*)&As[k][64 + ty * 4];
            *(float4*)(rb)     = *(const float4*)&Bs[k][tx * 4];
            *(float4*)(rb + 4) = *(const float4*)&Bs[k][64 + tx * 4];
#pragma unroll
            for (int i = 0; i < 8; i++)
#pragma unroll
                for (int j = 0; j < 8; j++) acc[i][j] += ra[i] * rb[j];
        }
        __syncthreads();
    }

#pragma unroll
    for (int i = 0; i < 8; i++) {
        int gm = m0 + ((i < 4) ? (ty * 4 + i) : (60 + ty * 4 + i));
        if (MODE == 0) {
#pragma unroll
            for (int j = 0; j < 8; j++) {
                int gn = n0 + ((j < 4) ? (tx * 4 + j) : (60 + tx * 4 + j));
                out[(long)gm * ldo + gn] = acc[i][j] + bias[gn];
            }
        } else {
#pragma unroll
            for (int half = 0; half < 2; half++) {
                int j = (n0 >> 2) + tx + half * 16;   // hidden unit index
                float xi = acc[i][half * 4 + 0] + bias[4 * j + 0];
                float xf = acc[i][half * 4 + 1] + bias[4 * j + 1];
                float xg = acc[i][half * 4 + 2] + bias[4 * j + 2];
                float xo = acc[i][half * 4 + 3] + bias[4 * j + 3];
                float c  = cst[(long)gm * HID + j];
                float cn = sigf(xf) * c + sigf(xi) * tanhf(xg);
                float hn = sigf(xo) * tanhf(cn);
                cst[(long)gm * HID + j] = cn;
                hdst[(long)gm * ldh + hoff + j] = hn;
            }
        }
    }
}

// ---------------- small GEMM: 64x64 tile, 256 threads, 4x4/thread ----------------
// MODE 0: out = C + bias ;  MODE 2: output step (write d_out[t] and feed back into A1)
template <int MODE>
__global__ void __launch_bounds__(256) gemm64(
    const float* __restrict__ A, int lda, int K,
    const float* __restrict__ W,
    const float* __restrict__ bias,
    float* __restrict__ out, int ldo, int t)
{
    __shared__ float As[16][68];
    __shared__ float Bs[16][68];

    const int tid = threadIdx.x;
    const int tx = tid & 15, ty = tid >> 4;
    const int m0 = blockIdx.x * 64, n0 = blockIdx.y * 64;

    float acc[4][4];
#pragma unroll
    for (int i = 0; i < 4; i++)
#pragma unroll
        for (int j = 0; j < 4; j++) acc[i][j] = 0.0f;

    const float* Ag = A + (long)m0 * lda;
    const float* Wg = W + (long)n0 * K;

    for (int k0 = 0; k0 < K; k0 += 16) {
        {
            int r = tid >> 2, kq = (tid & 3) * 4;
            float4 fa = *(const float4*)(Ag + (long)r * lda + k0 + kq);
            As[kq + 0][r] = fa.x; As[kq + 1][r] = fa.y;
            As[kq + 2][r] = fa.z; As[kq + 3][r] = fa.w;
            float4 fb = *(const float4*)(Wg + (long)r * K + k0 + kq);
            Bs[kq + 0][r] = fb.x; Bs[kq + 1][r] = fb.y;
            Bs[kq + 2][r] = fb.z; Bs[kq + 3][r] = fb.w;
        }
        __syncthreads();
#pragma unroll
        for (int k = 0; k < 16; k++) {
            float ra[4], rb[4];
            *(float4*)ra = *(const float4*)&As[k][ty * 4];
            *(float4*)rb = *(const float4*)&Bs[k][tx * 4];
#pragma unroll
            for (int i = 0; i < 4; i++)
#pragma unroll
                for (int j = 0; j < 4; j++) acc[i][j] += ra[i] * rb[j];
        }
        __syncthreads();
    }

#pragma unroll
    for (int i = 0; i < 4; i++) {
        int gm = m0 + ty * 4 + i;
#pragma unroll
        for (int j = 0; j < 4; j++) {
            int gn = n0 + tx * 4 + j;
            float y = acc[i][j] + bias[gn];
            if (MODE == 0) {
                out[(long)gm * ldo + gn] = y;
            } else {
                out[((long)gm * SEQ + t) * OUTD + gn] = y;   // d_out[m][t][n]
                g_A1[(long)gm * KC1 + gn] = y;               // x(t+1)
            }
        }
    }
}

// ---------------- init LN+GELU over 2048, scatter h0/c0, zero x ----------------
__global__ void init_ln(const float* __restrict__ ln1_w, const float* __restrict__ ln1_b) {
    __shared__ float red[256];
    const int m = blockIdx.x, tid = threadIdx.x;
    const float* row = g_H0 + (long)m * 2048;

    float v[8], s = 0.f;
#pragma unroll
    for (int i = 0; i < 8; i++) { v[i] = row[tid + i * 256]; s += v[i]; }
    red[tid] = s; __syncthreads();
    for (int o = 128; o > 0; o >>= 1) { if (tid < o) red[tid] += red[tid + o]; __syncthreads(); }
    float mu = red[0] * (1.0f / 2048.0f);
    __syncthreads();

    float vs = 0.f;
#pragma unroll
    for (int i = 0; i < 8; i++) { float d = v[i] - mu; vs += d * d; }
    red[tid] = vs; __syncthreads();
    for (int o = 128; o > 0; o >>= 1) { if (tid < o) red[tid] += red[tid + o]; __syncthreads(); }
    float rstd = rsqrtf(red[0] * (1.0f / 2048.0f) + 1e-5f);

#pragma unroll
    for (int i = 0; i < 8; i++) {
        int c = tid + i * 256;
        float y = geluf((v[i] - mu) * rstd * ln1_w[c] + ln1_b[c]);
        if (c < HID) {
            g_A1[(long)m * KC1 + OUTD + c] = y;   // h1 = h0
            g_A2[(long)m * KC2 + c]        = y;   // h1 slot in A2
            g_A2[(long)m * KC2 + HID + c]  = y;   // h2 = h0
        } else {
            g_C1[(long)m * HID + (c - HID)] = y;  // c1 = c0
            g_C2[(long)m * HID + (c - HID)] = y;  // c2 = c0
        }
    }
    if (tid < OUTD) g_A1[(long)m * KC1 + tid] = 0.f;  // x0 = 0
}

// ---------------- per-step LN+GELU (in place on g_P) + state rotation copies ----------------
__global__ void step_ln(const float* __restrict__ pln_w, const float* __restrict__ pln_b) {
    __shared__ float red[256];
    const int m = blockIdx.x, tid = threadIdx.x;
    float* prow = g_P + (long)m * HID;

    float v[4], s = 0.f;
#pragma unroll
    for (int i = 0; i < 4; i++) { v[i] = prow[tid + i * 256]; s += v[i]; }
    red[tid] = s; __syncthreads();
    for (int o = 128; o > 0; o >>= 1) { if (tid < o) red[tid] += red[tid + o]; __syncthreads(); }
    float mu = red[0] * (1.0f / 1024.0f);
    __syncthreads();

    float vs = 0.f;
#pragma unroll
    for (int i = 0; i < 4; i++) { float d = v[i] - mu; vs += d * d; }
    red[tid] = vs; __syncthreads();
    for (int o = 128; o > 0; o >>= 1) { if (tid < o) red[tid] += red[tid + o]; __syncthreads(); }
    float rstd = rsqrtf(red[0] * (1.0f / 1024.0f) + 1e-5f);

#pragma unroll
    for (int i = 0; i < 4; i++) {
        int c = tid + i * 256;
        prow[c] = geluf((v[i] - mu) * rstd * pln_w[c] + pln_b[c]);
        // rotate states for next step (safe: neither buffer is an input of a kernel
        // running concurrently; this kernel is the only writer at this point)
        g_A1[(long)m * KC1 + OUTD + c] = g_A2[(long)m * KC2 + c];   // h1 -> A1
        g_A2[(long)m * KC2 + HID + c]  = g_H2[(long)m * HID + c];   // h2 -> A2
    }
}

// ---------------- host ----------------
extern "C" void kernel_launch(void* const* d_in, const int* in_sizes, int n_in,
                              void* d_out, int out_size) {
    const float* z      = (const float*)d_in[0];
    const float* lin1_w = (const float*)d_in[1];
    const float* lin1_b = (const float*)d_in[2];
    const float* ln1_w  = (const float*)d_in[3];
    const float* ln1_b  = (const float*)d_in[4];
    const float* w_ih0  = (const float*)d_in[5];
    const float* w_hh0  = (const float*)d_in[6];
    const float* b0     = (const float*)d_in[7];
    const float* w_ih1  = (const float*)d_in[8];
    const float* w_hh1  = (const float*)d_in[9];
    const float* b1     = (const float*)d_in[10];
    const float* p1_w   = (const float*)d_in[11];
    const float* p1_b   = (const float*)d_in[12];
    const float* pln_w  = (const float*)d_in[13];
    const float* pln_b  = (const float*)d_in[14];
    const float* p2_w   = (const float*)d_in[15];
    const float* p2_b   = (const float*)d_in[16];
    float* out = (float*)d_out;

    float *A1, *A2, *C1, *C2, *H2, *P, *H0, *W1, *W2, *B1, *B2;
    cudaGetSymbolAddress((void**)&A1, g_A1);
    cudaGetSymbolAddress((void**)&A2, g_A2);
    cudaGetSymbolAddress((void**)&C1, g_C1);
    cudaGetSymbolAddress((void**)&C2, g_C2);
    cudaGetSymbolAddress((void**)&H2, g_H2);
    cudaGetSymbolAddress((void**)&P,  g_P);
    cudaGetSymbolAddress((void**)&H0, g_H0);
    cudaGetSymbolAddress((void**)&W1, g_W1);
    cudaGetSymbolAddress((void**)&W2, g_W2);
    cudaGetSymbolAddress((void**)&B1, g_B1);
    cudaGetSymbolAddress((void**)&B2, g_B2);

    // one-time-per-call weight reorder (cheap, ~50MB of copies)
    prep_weights<<<2048, 256>>>(w_ih0, w_hh0, b0, w_ih1, w_hh1, b1);

    // init: H0 = z @ lin1_w.T + lin1_b   (M=512, N=2048, K=256)
    gemm128<0><<<dim3(4, 16), 256>>>(z, LATENT, LATENT, lin1_w, lin1_b,
                                     H0, 2 * HID, nullptr, nullptr, 0, 0);
    init_ln<<<BATCH, 256>>>(ln1_w, ln1_b);

    for (int t = 0; t < SEQ; t++) {
        // cell 1: gates = A1 @ W1.T + B1, epilogue -> C1, h1 into A2[:, 0:HID]
        gemm128<1><<<dim3(4, 32), 256>>>(A1, KC1, KC1, W1, B1,
                                         nullptr, 0, C1, A2, KC2, 0);
        // cell 2: gates = A2 @ W2.T + B2, epilogue -> C2, h2 into H2
        gemm128<1><<<dim3(4, 32), 256>>>(A2, KC2, KC2, W2, B2,
                                         nullptr, 0, C2, H2, HID, 0);
        // p1 projection: P = H2 @ p1_w.T + p1_b  (M=512, N=1024, K=1024)
        gemm64<0><<<dim3(8, 16), 256>>>(H2, HID, HID, p1_w, p1_b, P, HID, 0);
        // LN + gelu (in place) + rotate h1->A1, h2->A2
        step_ln<<<BATCH, 256>>>(pln_w, pln_b);
        // output: y = P @ p2_w.T + p2_b -> d_out[:, t, :] and A1[:, 0:128]
        gemm64<2><<<dim3(8, 2), 256>>>(P, HID, HID, p2_w, p2_b, out, 0, t);
    }
}

// round 3
// speedup vs baseline: 2.3766x; 2.3766x over previous
#include <cuda_runtime.h>
#include <cuda_bf16.h>
#include <math.h>
#include <stdint.h>

#define BATCH 512
#define LATENT 256
#define HID 1024
#define OUTD 128
#define SEQ 96
#define G4 4096
#define KC1 1152
#define KC2 2048

typedef __nv_bfloat16 bf16;

// ---------------- static device scratch ----------------
__device__ bf16 g_A1h[BATCH * KC1], g_A1l[BATCH * KC1];   // [x | h1] pairs
__device__ bf16 g_A2h[BATCH * KC2], g_A2l[BATCH * KC2];   // [h1 | h2] pairs
__device__ bf16 g_H2h[BATCH * HID], g_H2l[BATCH * HID];   // fresh h2 pairs
__device__ bf16 g_PPh[BATCH * HID], g_PPl[BATCH * HID];   // post-LN gelu pairs
__device__ float g_P[BATCH * HID];                        // p1 out fp32
__device__ float g_C1[BATCH * HID], g_C2[BATCH * HID];
__device__ float g_H0[BATCH * 2 * HID];
__device__ bf16 g_Zh[BATCH * LATENT], g_Zl[BATCH * LATENT];
__device__ bf16 g_W1h[G4 * KC1], g_W1l[G4 * KC1];         // gate-permuted cols
__device__ bf16 g_W2h[G4 * KC2], g_W2l[G4 * KC2];
__device__ bf16 g_WLh[2 * HID * LATENT], g_WLl[2 * HID * LATENT];
__device__ bf16 g_P1h[HID * HID], g_P1l[HID * HID];
__device__ bf16 g_P2h[OUTD * HID], g_P2l[OUTD * HID];
__device__ float g_B1[G4], g_B2[G4];                      // gate-permuted

// ---------------- helpers ----------------
__device__ __forceinline__ uint32_t smem_u32(const void* p) {
    uint32_t a;
    asm("{ .reg .u64 t; cvta.to.shared.u64 t, %1; cvt.u32.u64 %0, t; }" : "=r"(a) : "l"(p));
    return a;
}
__device__ __forceinline__ void cpa16(uint32_t dst, const void* src) {
    asm volatile("cp.async.cg.shared.global [%0], [%1], 16;" :: "r"(dst), "l"(src));
}
__device__ __forceinline__ void ldsm4(uint32_t* r, uint32_t a) {
    asm volatile("ldmatrix.sync.aligned.m8n8.x4.shared.b16 {%0,%1,%2,%3}, [%4];"
        : "=r"(r[0]), "=r"(r[1]), "=r"(r[2]), "=r"(r[3]) : "r"(a));
}
__device__ __forceinline__ void ldsm2(uint32_t* r, uint32_t a) {
    asm volatile("ldmatrix.sync.aligned.m8n8.x2.shared.b16 {%0,%1}, [%2];"
        : "=r"(r[0]), "=r"(r[1]) : "r"(a));
}
__device__ __forceinline__ void mma16816(float* c, const uint32_t* a, const uint32_t* b) {
    asm volatile("mma.sync.aligned.m16n8k16.row.col.f32.bf16.bf16.f32 "
        "{%0,%1,%2,%3}, {%4,%5,%6,%7}, {%8,%9}, {%0,%1,%2,%3};"
        : "+f"(c[0]), "+f"(c[1]), "+f"(c[2]), "+f"(c[3])
        : "r"(a[0]), "r"(a[1]), "r"(a[2]), "r"(a[3]), "r"(b[0]), "r"(b[1]));
}
__device__ __forceinline__ float sigf(float x) { return 1.0f / (1.0f + __expf(-x)); }
__device__ __forceinline__ float geluf(float x) {
    return 0.5f * x * (1.0f + erff(x * 0.70710678118654752f));
}
__device__ __forceinline__ void split2(float v, bf16* ph, bf16* pl) {
    bf16 h = __float2bfloat16(v);
    *ph = h;
    *pl = __float2bfloat16(v - __bfloat162float(h));
}
__device__ __forceinline__ uint32_t swz(uint32_t off) { return off ^ ((off >> 3) & 0x70); }

#define SMEM_BYTES 132096   // 2 x 64KB buffers + align slack

// ---------------- tensor-core GEMM via mma.sync, C = A @ W^T, bf16x2 split ------
// MODE 0: out[m*ldo+n] = C + bias[n]  (fp32, plain columns)
// MODE 1: LSTM epilogue (gate-permuted columns), h -> (hh,hl), c in cst
// MODE 2: y = C + bias -> d_out[m][t][n] and (hh,hl) at cols [0,OUTD)
template <int MODE>
__global__ void __launch_bounds__(256) mmagemm(
    const bf16* __restrict__ Ah, const bf16* __restrict__ Al, int K,
    const bf16* __restrict__ Wh, const bf16* __restrict__ Wl,
    const float* __restrict__ bias,
    float* __restrict__ out, int ldo,
    float* __restrict__ cst,
    bf16* __restrict__ hh, bf16* __restrict__ hl, int ldh,
    int t)
{
    extern __shared__ char smem_raw[];
    uint32_t sb_raw = smem_u32(smem_raw);
    uint32_t sb = (sb_raw + 1023u) & ~1023u;

    const int tid = threadIdx.x, wid = tid >> 5, lane = tid & 31;
    const int m0 = blockIdx.x * 128, n0 = blockIdx.y * 128;
    const int wm = wid >> 2, wn = wid & 3;     // warp tile: 64 (m) x 32 (n)
    const int g8 = lane >> 2, t4 = lane & 3;

    float acc[4][4][4];
#pragma unroll
    for (int a = 0; a < 4; a++)
#pragma unroll
        for (int b = 0; b < 4; b++)
#pragma unroll
            for (int r = 0; r < 4; r++) acc[a][b][r] = 0.0f;

    const int nc = K >> 6;

    // loader lambda-ish (macro by hand): chunk c -> buffer (c&1)
#define ISSUE_LOAD(cc) do {                                                      \
    uint32_t buf = sb + ((cc) & 1) * 65536;                                      \
    const long kof = (long)(cc) * 64;                                            \
    _Pragma("unroll")                                                            \
    for (int i = 0; i < 4; i++) {                                                \
        int idx = tid + i * 256;                                                 \
        int r = idx >> 3, cq = idx & 7;                                          \
        uint32_t so = swz((uint32_t)(r * 128 + cq * 16));                        \
        long ka = (long)(m0 + r) * K + kof + cq * 8;                             \
        long kw = (long)(n0 + r) * K + kof + cq * 8;                             \
        cpa16(buf + so,         Ah + ka);                                        \
        cpa16(buf + 16384 + so, Al + ka);                                        \
        cpa16(buf + 32768 + so, Wh + kw);                                        \
        cpa16(buf + 49152 + so, Wl + kw);                                        \
    }                                                                            \
    asm volatile("cp.async.commit_group;" ::: "memory");                         \
} while (0)

    ISSUE_LOAD(0);

    for (int c = 0; c < nc; c++) {
        if (c + 1 < nc) {
            ISSUE_LOAD(c + 1);
            asm volatile("cp.async.wait_group 1;" ::: "memory");
        } else {
            asm volatile("cp.async.wait_group 0;" ::: "memory");
        }
        __syncthreads();

        uint32_t Abase = sb + (c & 1) * 65536;
        uint32_t Wbase = Abase + 32768;
#pragma unroll
        for (int ks = 0; ks < 4; ks++) {
            uint32_t ah[4][4], al[4][4];
#pragma unroll
            for (int mi = 0; mi < 4; mi++) {
                int r = wm * 64 + mi * 16 + (lane & 15);
                int kb = ks * 32 + (lane >> 4) * 16;
                uint32_t so = swz((uint32_t)(r * 128 + kb));
                ldsm4(ah[mi], Abase + so);
                ldsm4(al[mi], Abase + 16384 + so);
            }
            uint32_t bh[4][2], bl[4][2];
#pragma unroll
            for (int g = 0; g < 4; g++) {
                int r = wn * 32 + g * 8 + (lane & 7);
                int kb = ks * 32 + ((lane >> 3) & 1) * 16;
                uint32_t so = swz((uint32_t)(r * 128 + kb));
                ldsm2(bh[g], Wbase + so);
                ldsm2(bl[g], Wbase + 16384 + so);
            }
#pragma unroll
            for (int mi = 0; mi < 4; mi++)
#pragma unroll
                for (int g = 0; g < 4; g++) {
                    mma16816(acc[mi][g], ah[mi], bh[g]);
                    mma16816(acc[mi][g], ah[mi], bl[g]);
                    mma16816(acc[mi][g], al[mi], bh[g]);
                }
        }
        __syncthreads();
    }
#undef ISSUE_LOAD

    // ---------------- epilogues ----------------
    if (MODE == 0) {
#pragma unroll
        for (int mi = 0; mi < 4; mi++) {
            int r0 = m0 + wm * 64 + mi * 16 + g8;
#pragma unroll
            for (int ni = 0; ni < 4; ni++) {
                int n = n0 + wn * 32 + ni * 8 + 2 * t4;
                float b0v = bias[n], b1v = bias[n + 1];
                float2 v0 = make_float2(acc[mi][ni][0] + b0v, acc[mi][ni][1] + b1v);
                float2 v1 = make_float2(acc[mi][ni][2] + b0v, acc[mi][ni][3] + b1v);
                *(float2*)(out + (long)r0 * ldo + n) = v0;
                *(float2*)(out + (long)(r0 + 8) * ldo + n) = v1;
            }
        }
    } else if (MODE == 1) {
        const int nb = n0 + wn * 32;
        const int j0 = (nb >> 5) * 8 + 2 * t4;     // units j0, j0+1
        float bg[4][2];
#pragma unroll
        for (int g = 0; g < 4; g++) {
            bg[g][0] = bias[nb + g * 8 + 2 * t4];
            bg[g][1] = bias[nb + g * 8 + 2 * t4 + 1];
        }
#pragma unroll
        for (int mi = 0; mi < 4; mi++) {
            int r0 = m0 + wm * 64 + mi * 16 + g8;
#pragma unroll
            for (int rr = 0; rr < 2; rr++) {
                int m = r0 + rr * 8;
                const long crow = (long)m * HID;
                const long hrow = (long)m * ldh;
#pragma unroll
                for (int u = 0; u < 2; u++) {
                    int j = j0 + u;
                    int reg = rr * 2 + u;
                    float xi = acc[mi][0][reg] + bg[0][u];
                    float xf = acc[mi][1][reg] + bg[1][u];
                    float xg = acc[mi][2][reg] + bg[2][u];
                    float xo = acc[mi][3][reg] + bg[3][u];
                    float cold = cst[crow + j];
                    float cn = sigf(xf) * cold + sigf(xi) * tanhf(xg);
                    float hn = sigf(xo) * tanhf(cn);
                    cst[crow + j] = cn;
                    bf16 h = __float2bfloat16(hn);
                    hh[hrow + j] = h;
                    hl[hrow + j] = __float2bfloat16(hn - __bfloat162float(h));
                }
            }
        }
    } else {  // MODE 2
#pragma unroll
        for (int mi = 0; mi < 4; mi++) {
            int r0 = m0 + wm * 64 + mi * 16 + g8;
#pragma unroll
            for (int ni = 0; ni < 4; ni++) {
                int n = wn * 32 + ni * 8 + 2 * t4;
                float b0v = bias[n], b1v = bias[n + 1];
#pragma unroll
                for (int rr = 0; rr < 2; rr++) {
                    int m = r0 + rr * 8;
                    float y0 = acc[mi][ni][rr * 2 + 0] + b0v;
                    float y1 = acc[mi][ni][rr * 2 + 1] + b1v;
                    float2 v = make_float2(y0, y1);
                    *(float2*)(out + ((long)m * SEQ + t) * OUTD + n) = v;
                    bf16 h0 = __float2bfloat16(y0), h1 = __float2bfloat16(y1);
                    hh[(long)m * ldh + n] = h0;
                    hh[(long)m * ldh + n + 1] = h1;
                    hl[(long)m * ldh + n] = __float2bfloat16(y0 - __bfloat162float(h0));
                    hl[(long)m * ldh + n + 1] = __float2bfloat16(y1 - __bfloat162float(h1));
                }
            }
        }
    }
}

// ---------------- prep: split + permute weights -------------
// gate permutation: gemm col n <- orig row g*HID + j, with
//   g = (n>>3)&3,  j = (n>>5)*8 + (n&7)
__global__ void prep(const float* __restrict__ z, const float* __restrict__ lin1_w,
                     const float* __restrict__ w_ih0, const float* __restrict__ w_hh0,
                     const float* __restrict__ b0,
                     const float* __restrict__ w_ih1, const float* __restrict__ w_hh1,
                     const float* __restrict__ b1,
                     const float* __restrict__ p1_w, const float* __restrict__ p2_w) {
    long stride = (long)gridDim.x * blockDim.x;
    long i0 = (long)blockIdx.x * blockDim.x + threadIdx.x;

    for (long idx = i0; idx < (long)G4 * KC1; idx += stride) {
        int n = (int)(idx / KC1), k = (int)(idx % KC1);
        int g = (n >> 3) & 3, j = (n >> 5) * 8 + (n & 7), sr = g * HID + j;
        float v = (k < OUTD) ? w_ih0[(long)sr * OUTD + k] : w_hh0[(long)sr * HID + (k - OUTD)];
        split2(v, &g_W1h[idx], &g_W1l[idx]);
    }
    for (long idx = i0; idx < (long)G4 * KC2; idx += stride) {
        int n = (int)(idx / KC2), k = (int)(idx % KC2);
        int g = (n >> 3) & 3, j = (n >> 5) * 8 + (n & 7), sr = g * HID + j;
        float v = (k < HID) ? w_ih1[(long)sr * HID + k] : w_hh1[(long)sr * HID + (k - HID)];
        split2(v, &g_W2h[idx], &g_W2l[idx]);
    }
    for (long idx = i0; idx < (long)2 * HID * LATENT; idx += stride)
        split2(lin1_w[idx], &g_WLh[idx], &g_WLl[idx]);
    for (long idx = i0; idx < (long)HID * HID; idx += stride)
        split2(p1_w[idx], &g_P1h[idx], &g_P1l[idx]);
    for (long idx = i0; idx < (long)OUTD * HID; idx += stride)
        split2(p2_w[idx], &g_P2h[idx], &g_P2l[idx]);
    for (long idx = i0; idx < (long)BATCH * LATENT; idx += stride)
        split2(z[idx], &g_Zh[idx], &g_Zl[idx]);
    for (long idx = i0; idx < G4; idx += stride) {
        int n = (int)idx;
        int g = (n >> 3) & 3, j = (n >> 5) * 8 + (n & 7);
        g_B1[n] = b0[g * HID + j];
        g_B2[n] = b1[g * HID + j];
    }
}

// ---------------- init LN+GELU over 2048 ----------------
__global__ void init_ln(const float* __restrict__ ln1_w, const float* __restrict__ ln1_b) {
    __shared__ float red[256];
    const int m = blockIdx.x, tid = threadIdx.x;
    const float* row = g_H0 + (long)m * 2048;

    float v[8], s = 0.f;
#pragma unroll
    for (int i = 0; i < 8; i++) { v[i] = row[tid + i * 256]; s += v[i]; }
    red[tid] = s; __syncthreads();
    for (int o = 128; o > 0; o >>= 1) { if (tid < o) red[tid] += red[tid + o]; __syncthreads(); }
    float mu = red[0] * (1.0f / 2048.0f);
    __syncthreads();
    float vs = 0.f;
#pragma unroll
    for (int i = 0; i < 8; i++) { float dd = v[i] - mu; vs += dd * dd; }
    red[tid] = vs; __syncthreads();
    for (int o = 128; o > 0; o >>= 1) { if (tid < o) red[tid] += red[tid + o]; __syncthreads(); }
    float rstd = rsqrtf(red[0] * (1.0f / 2048.0f) + 1e-5f);

#pragma unroll
    for (int i = 0; i < 8; i++) {
        int c = tid + i * 256;
        float y = geluf((v[i] - mu) * rstd * ln1_w[c] + ln1_b[c]);
        if (c < HID) {
            bf16 h = __float2bfloat16(y);
            bf16 l = __float2bfloat16(y - __bfloat162float(h));
            g_A1h[(long)m * KC1 + OUTD + c] = h;  g_A1l[(long)m * KC1 + OUTD + c] = l;
            g_A2h[(long)m * KC2 + c] = h;         g_A2l[(long)m * KC2 + c] = l;
            g_A2h[(long)m * KC2 + HID + c] = h;   g_A2l[(long)m * KC2 + HID + c] = l;
        } else {
            g_C1[(long)m * HID + (c - HID)] = y;
            g_C2[(long)m * HID + (c - HID)] = y;
        }
    }
    if (tid < OUTD) {
        g_A1h[(long)m * KC1 + tid] = __float2bfloat16(0.f);
        g_A1l[(long)m * KC1 + tid] = __float2bfloat16(0.f);
    }
}

// ---------------- per-step LN+GELU -> PP pairs, rotate h1/h2 ----------------
__global__ void step_ln(const float* __restrict__ pln_w, const float* __restrict__ pln_b) {
    __shared__ float red[256];
    const int m = blockIdx.x, tid = threadIdx.x;
    const float* prow = g_P + (long)m * HID;

    float v[4], s = 0.f;
#pragma unroll
    for (int i = 0; i < 4; i++) { v[i] = prow[tid + i * 256]; s += v[i]; }
    red[tid] = s; __syncthreads();
    for (int o = 128; o > 0; o >>= 1) { if (tid < o) red[tid] += red[tid + o]; __syncthreads(); }
    float mu = red[0] * (1.0f / 1024.0f);
    __syncthreads();
    float vs = 0.f;
#pragma unroll
    for (int i = 0; i < 4; i++) { float dd = v[i] - mu; vs += dd * dd; }
    red[tid] = vs; __syncthreads();
    for (int o = 128; o > 0; o >>= 1) { if (tid < o) red[tid] += red[tid + o]; __syncthreads(); }
    float rstd = rsqrtf(red[0] * (1.0f / 1024.0f) + 1e-5f);

#pragma unroll
    for (int i = 0; i < 4; i++) {
        int c = tid + i * 256;
        float y = geluf((v[i] - mu) * rstd * pln_w[c] + pln_b[c]);
        bf16 h = __float2bfloat16(y);
        g_PPh[(long)m * HID + c] = h;
        g_PPl[(long)m * HID + c] = __float2bfloat16(y - __bfloat162float(h));
        g_A1h[(long)m * KC1 + OUTD + c] = g_A2h[(long)m * KC2 + c];
        g_A1l[(long)m * KC1 + OUTD + c] = g_A2l[(long)m * KC2 + c];
        g_A2h[(long)m * KC2 + HID + c] = g_H2h[(long)m * HID + c];
        g_A2l[(long)m * KC2 + HID + c] = g_H2l[(long)m * HID + c];
    }
}

// ---------------- host ----------------
extern "C" void kernel_launch(void* const* d_in, const int* in_sizes, int n_in,
                              void* d_out, int out_size) {
    const float* z      = (const float*)d_in[0];
    const float* lin1_w = (const float*)d_in[1];
    const float* lin1_b = (const float*)d_in[2];
    const float* ln1_w  = (const float*)d_in[3];
    const float* ln1_b  = (const float*)d_in[4];
    const float* w_ih0  = (const float*)d_in[5];
    const float* w_hh0  = (const float*)d_in[6];
    const float* b0     = (const float*)d_in[7];
    const float* w_ih1  = (const float*)d_in[8];
    const float* w_hh1  = (const float*)d_in[9];
    const float* b1     = (const float*)d_in[10];
    const float* p1_w   = (const float*)d_in[11];
    const float* p1_b   = (const float*)d_in[12];
    const float* pln_w  = (const float*)d_in[13];
    const float* pln_b  = (const float*)d_in[14];
    const float* p2_w   = (const float*)d_in[15];
    const float* p2_b   = (const float*)d_in[16];
    float* out = (float*)d_out;

    bf16 *A1h, *A1l, *A2h, *A2l, *H2h, *H2l, *PPh, *PPl;
    bf16 *Zh, *Zl, *W1h, *W1l, *W2h, *W2l, *WLh, *WLl, *P1h, *P1l, *P2h, *P2l;
    float *P, *C1, *C2, *H0, *B1, *B2;
    cudaGetSymbolAddress((void**)&A1h, g_A1h); cudaGetSymbolAddress((void**)&A1l, g_A1l);
    cudaGetSymbolAddress((void**)&A2h, g_A2h); cudaGetSymbolAddress((void**)&A2l, g_A2l);
    cudaGetSymbolAddress((void**)&H2h, g_H2h); cudaGetSymbolAddress((void**)&H2l, g_H2l);
    cudaGetSymbolAddress((void**)&PPh, g_PPh); cudaGetSymbolAddress((void**)&PPl, g_PPl);
    cudaGetSymbolAddress((void**)&Zh, g_Zh);   cudaGetSymbolAddress((void**)&Zl, g_Zl);
    cudaGetSymbolAddress((void**)&W1h, g_W1h); cudaGetSymbolAddress((void**)&W1l, g_W1l);
    cudaGetSymbolAddress((void**)&W2h, g_W2h); cudaGetSymbolAddress((void**)&W2l, g_W2l);
    cudaGetSymbolAddress((void**)&WLh, g_WLh); cudaGetSymbolAddress((void**)&WLl, g_WLl);
    cudaGetSymbolAddress((void**)&P1h, g_P1h); cudaGetSymbolAddress((void**)&P1l, g_P1l);
    cudaGetSymbolAddress((void**)&P2h, g_P2h); cudaGetSymbolAddress((void**)&P2l, g_P2l);
    cudaGetSymbolAddress((void**)&P, g_P);
    cudaGetSymbolAddress((void**)&C1, g_C1);   cudaGetSymbolAddress((void**)&C2, g_C2);
    cudaGetSymbolAddress((void**)&H0, g_H0);
    cudaGetSymbolAddress((void**)&B1, g_B1);   cudaGetSymbolAddress((void**)&B2, g_B2);

    cudaFuncSetAttribute(mmagemm<0>, cudaFuncAttributeMaxDynamicSharedMemorySize, SMEM_BYTES);
    cudaFuncSetAttribute(mmagemm<1>, cudaFuncAttributeMaxDynamicSharedMemorySize, SMEM_BYTES);
    cudaFuncSetAttribute(mmagemm<2>, cudaFuncAttributeMaxDynamicSharedMemorySize, SMEM_BYTES);

    prep<<<2048, 256>>>(z, lin1_w, w_ih0, w_hh0, b0, w_ih1, w_hh1, b1, p1_w, p2_w);

    // init: H0 = z @ lin1_w^T + lin1_b   (M=512, N=2048, K=256)
    mmagemm<0><<<dim3(4, 16), 256, SMEM_BYTES>>>(Zh, Zl, LATENT, WLh, WLl, lin1_b,
                                                 H0, 2 * HID, nullptr, nullptr, nullptr, 0, 0);
    init_ln<<<BATCH, 256>>>(ln1_w, ln1_b);

    for (int t = 0; t < SEQ; t++) {
        // cell 1: gates = A1 @ W1^T + B1 -> LSTM epi, h1 pairs into A2[:, 0:HID]
        mmagemm<1><<<dim3(4, 32), 256, SMEM_BYTES>>>(A1h, A1l, KC1, W1h, W1l, B1,
                                                     nullptr, 0, C1, A2h, A2l, KC2, 0);
        // cell 2: gates = A2 @ W2^T + B2 -> LSTM epi, h2 pairs into H2
        mmagemm<1><<<dim3(4, 32), 256, SMEM_BYTES>>>(A2h, A2l, KC2, W2h, W2l, B2,
                                                     nullptr, 0, C2, H2h, H2l, HID, 0);
        // p1: P = H2 @ p1_w^T + p1_b  (fp32, M=512, N=1024, K=1024)
        mmagemm<0><<<dim3(4, 8), 256, SMEM_BYTES>>>(H2h, H2l, HID, P1h, P1l, p1_b,
                                                    P, HID, nullptr, nullptr, nullptr, 0, 0);
        // LN + gelu -> PP pairs, rotate h1 -> A1, h2 -> A2
        step_ln<<<BATCH, 256>>>(pln_w, pln_b);
        // output: y = PP @ p2_w^T + p2_b -> d_out[:, t, :] and A1[:, 0:128] pairs
        mmagemm<2><<<dim3(4, 1), 256, SMEM_BYTES>>>(PPh, PPl, HID, P2h, P2l, p2_b,
                                                    out, 0, nullptr, A1h, A1l, KC1, t);
    }
}

// round 6
// speedup vs baseline: 3.0415x; 1.2798x over previous
#include <cuda_runtime.h>
#include <cuda_bf16.h>
#include <math.h>
#include <stdint.h>

#define BATCH 512
#define LATENT 256
#define HID 1024
#define OUTD 128
#define SEQ 96
#define G4 4096
#define KC1 1152
#define KC2 2048

typedef __nv_bfloat16 bf16;

// ---------------- static device scratch (ping-pong state) ----------------
__device__ bf16 g_A1h[2][BATCH * KC1], g_A1l[2][BATCH * KC1];   // [x | h1]
__device__ bf16 g_A2h[2][BATCH * KC2], g_A2l[2][BATCH * KC2];   // [h1 | h2]
__device__ bf16 g_H2h[BATCH * HID], g_H2l[BATCH * HID];         // fresh h2
__device__ bf16 g_PPh[BATCH * HID], g_PPl[BATCH * HID];         // post-LN gelu
__device__ float g_P[BATCH * HID];
__device__ float g_C1[BATCH * HID], g_C2[BATCH * HID];
__device__ float g_H0[BATCH * 2 * HID];
__device__ bf16 g_Zh[BATCH * LATENT], g_Zl[BATCH * LATENT];
__device__ bf16 g_W1h[G4 * KC1], g_W1l[G4 * KC1];
__device__ bf16 g_W2h[G4 * KC2], g_W2l[G4 * KC2];
__device__ bf16 g_WLh[2 * HID * LATENT], g_WLl[2 * HID * LATENT];
__device__ bf16 g_P1h[HID * HID], g_P1l[HID * HID];
__device__ bf16 g_P2h[OUTD * HID], g_P2l[OUTD * HID];
__device__ float g_B1[G4], g_B2[G4];

// ---------------- helpers ----------------
__device__ __forceinline__ uint32_t smem_u32(const void* p) {
    uint32_t a;
    asm("{ .reg .u64 t; cvta.to.shared.u64 t, %1; cvt.u32.u64 %0, t; }" : "=r"(a) : "l"(p));
    return a;
}
__device__ __forceinline__ void cpa16(uint32_t dst, const void* src) {
    asm volatile("cp.async.cg.shared.global [%0], [%1], 16;" :: "r"(dst), "l"(src));
}
__device__ __forceinline__ void ldsm4(uint32_t* r, uint32_t a) {
    asm volatile("ldmatrix.sync.aligned.m8n8.x4.shared.b16 {%0,%1,%2,%3}, [%4];"
        : "=r"(r[0]), "=r"(r[1]), "=r"(r[2]), "=r"(r[3]) : "r"(a));
}
__device__ __forceinline__ void mma16816(float* c, const uint32_t* a, const uint32_t* b) {
    asm volatile("mma.sync.aligned.m16n8k16.row.col.f32.bf16.bf16.f32 "
        "{%0,%1,%2,%3}, {%4,%5,%6,%7}, {%8,%9}, {%0,%1,%2,%3};"
        : "+f"(c[0]), "+f"(c[1]), "+f"(c[2]), "+f"(c[3])
        : "r"(a[0]), "r"(a[1]), "r"(a[2]), "r"(a[3]), "r"(b[0]), "r"(b[1]));
}
__device__ __forceinline__ float sigf(float x) { return 1.0f / (1.0f + __expf(-x)); }
__device__ __forceinline__ float geluf(float x) {
    return 0.5f * x * (1.0f + erff(x * 0.70710678118654752f));
}
__device__ __forceinline__ void split2(float v, bf16* ph, bf16* pl) {
    bf16 h = __float2bfloat16(v);
    *ph = h;
    *pl = __float2bfloat16(v - __bfloat162float(h));
}
__device__ __forceinline__ uint32_t swz(uint32_t off) { return off ^ ((off >> 3) & 0x70); }

// SMEM: per chunk 48KB: Ah 16K @0, Al 16K @16K, Wh 8K @32K, Wl 8K @40K. x2 buffers.
#define CHUNK_BYTES 49152
#define SMEM_BYTES (2 * CHUNK_BYTES + 1024)

// ---------------- GEMM: CTA tile 128(m) x 64(n), warp 32x32, bf16x2 split ------
// MODE 0: out[m*ldo+n] = C + bias[n]
// MODE 1: LSTM epilogue (gate-permuted cols); h -> (hh,hl) and (hh2,hl2); c in cst
// MODE 2: y -> d_out[m][t][n] and pairs (hh,hl) at cols [0,OUTD)
template <int MODE>
__global__ void __launch_bounds__(256, 2) mmagemm(
    const bf16* __restrict__ Ah, const bf16* __restrict__ Al, int K,
    const bf16* __restrict__ Wh, const bf16* __restrict__ Wl,
    const float* __restrict__ bias,
    float* __restrict__ out, int ldo,
    float* __restrict__ cst,
    bf16* __restrict__ hh, bf16* __restrict__ hl, int ldh,
    bf16* __restrict__ hh2, bf16* __restrict__ hl2, int ldh2,
    int t)
{
    extern __shared__ char smem_raw[];
    uint32_t sb_raw = smem_u32(smem_raw);
    uint32_t sb = (sb_raw + 1023u) & ~1023u;

    const int tid = threadIdx.x, wid = tid >> 5, lane = tid & 31;
    const int m0 = blockIdx.x * 128, n0 = blockIdx.y * 64;
    const int wm = wid >> 1, wn = wid & 1;       // warp tile 32(m) x 32(n)
    const int g8 = lane >> 2, t4 = lane & 3;

    float acc[2][4][4];
#pragma unroll
    for (int a = 0; a < 2; a++)
#pragma unroll
        for (int b = 0; b < 4; b++)
#pragma unroll
            for (int r = 0; r < 4; r++) acc[a][b][r] = 0.0f;

    const int nc = K >> 6;

#define ISSUE_LOAD(cc) do {                                                      \
    uint32_t buf = sb + ((cc) & 1) * CHUNK_BYTES;                                \
    const long kof = (long)(cc) * 64;                                            \
    _Pragma("unroll")                                                            \
    for (int i = 0; i < 4; i++) {                                                \
        int idx = tid + i * 256;                                                 \
        int r = idx >> 3, cq = idx & 7;                                          \
        uint32_t so = swz((uint32_t)(r * 128 + cq * 16));                        \
        long ka = (long)(m0 + r) * K + kof + cq * 8;                             \
        cpa16(buf + so,         Ah + ka);                                        \
        cpa16(buf + 16384 + so, Al + ka);                                        \
    }                                                                            \
    _Pragma("unroll")                                                            \
    for (int i = 0; i < 2; i++) {                                                \
        int idx = tid + i * 256;                                                 \
        int r = idx >> 3, cq = idx & 7;                                          \
        uint32_t so = swz((uint32_t)(r * 128 + cq * 16));                        \
        long kw = (long)(n0 + r) * K + kof + cq * 8;                             \
        cpa16(buf + 32768 + so, Wh + kw);                                        \
        cpa16(buf + 40960 + so, Wl + kw);                                        \
    }                                                                            \
    asm volatile("cp.async.commit_group;" ::: "memory");                         \
} while (0)

    ISSUE_LOAD(0);

    for (int c = 0; c < nc; c++) {
        if (c + 1 < nc) {
            ISSUE_LOAD(c + 1);
            asm volatile("cp.async.wait_group 1;" ::: "memory");
        } else {
            asm volatile("cp.async.wait_group 0;" ::: "memory");
        }
        __syncthreads();

        uint32_t Ab = sb + (c & 1) * CHUNK_BYTES;
        uint32_t Wb = Ab + 32768;
#pragma unroll
        for (int ks = 0; ks < 4; ks++) {
            uint32_t ah[2][4], al[2][4];
#pragma unroll
            for (int mi = 0; mi < 2; mi++) {
                int r = wm * 32 + mi * 16 + (lane & 15);
                int kb = ks * 32 + (lane >> 4) * 16;
                uint32_t so = swz((uint32_t)(r * 128 + kb));
                ldsm4(ah[mi], Ab + so);
                ldsm4(al[mi], Ab + 16384 + so);
            }
            // B: one ldsm4 per g-pair: regs {0,1}=g even, {2,3}=g odd
            uint32_t bh[2][4], bl[2][4];
#pragma unroll
            for (int gp = 0; gp < 2; gp++) {
                int r = wn * 32 + gp * 16 + ((lane >> 4) & 1) * 8 + (lane & 7);
                int kb = ks * 32 + ((lane >> 3) & 1) * 16;
                uint32_t so = swz((uint32_t)(r * 128 + kb));
                ldsm4(bh[gp], Wb + so);
                ldsm4(bl[gp], Wb + 8192 + so);
            }
#pragma unroll
            for (int mi = 0; mi < 2; mi++)
#pragma unroll
                for (int g = 0; g < 4; g++) {
                    const uint32_t* bhf = &bh[g >> 1][(g & 1) * 2];
                    const uint32_t* blf = &bl[g >> 1][(g & 1) * 2];
                    mma16816(acc[mi][g], ah[mi], bhf);
                    mma16816(acc[mi][g], ah[mi], blf);
                    mma16816(acc[mi][g], al[mi], bhf);
                }
        }
        __syncthreads();
    }
#undef ISSUE_LOAD

    // ---------------- epilogues ----------------
    if (MODE == 0) {
#pragma unroll
        for (int mi = 0; mi < 2; mi++) {
            int r0 = m0 + wm * 32 + mi * 16 + g8;
#pragma unroll
            for (int ni = 0; ni < 4; ni++) {
                int n = n0 + wn * 32 + ni * 8 + 2 * t4;
                float b0v = bias[n], b1v = bias[n + 1];
                float2 v0 = make_float2(acc[mi][ni][0] + b0v, acc[mi][ni][1] + b1v);
                float2 v1 = make_float2(acc[mi][ni][2] + b0v, acc[mi][ni][3] + b1v);
                *(float2*)(out + (long)r0 * ldo + n) = v0;
                *(float2*)(out + (long)(r0 + 8) * ldo + n) = v1;
            }
        }
    } else if (MODE == 1) {
        const int nb = n0 + wn * 32;
        const int j0 = (nb >> 5) * 8 + 2 * t4;
        float bg[4][2];
#pragma unroll
        for (int g = 0; g < 4; g++) {
            bg[g][0] = bias[nb + g * 8 + 2 * t4];
            bg[g][1] = bias[nb + g * 8 + 2 * t4 + 1];
        }
#pragma unroll
        for (int mi = 0; mi < 2; mi++) {
            int r0 = m0 + wm * 32 + mi * 16 + g8;
#pragma unroll
            for (int rr = 0; rr < 2; rr++) {
                int m = r0 + rr * 8;
                const long crow = (long)m * HID;
#pragma unroll
                for (int u = 0; u < 2; u++) {
                    int j = j0 + u;
                    int reg = rr * 2 + u;
                    float xi = acc[mi][0][reg] + bg[0][u];
                    float xf = acc[mi][1][reg] + bg[1][u];
                    float xg = acc[mi][2][reg] + bg[2][u];
                    float xo = acc[mi][3][reg] + bg[3][u];
                    float cold = cst[crow + j];
                    float cn = sigf(xf) * cold + sigf(xi) * tanhf(xg);
                    float hn = sigf(xo) * tanhf(cn);
                    cst[crow + j] = cn;
                    bf16 h = __float2bfloat16(hn);
                    bf16 l = __float2bfloat16(hn - __bfloat162float(h));
                    hh[(long)m * ldh + j] = h;
                    hl[(long)m * ldh + j] = l;
                    hh2[(long)m * ldh2 + j] = h;
                    hl2[(long)m * ldh2 + j] = l;
                }
            }
        }
    } else {  // MODE 2
#pragma unroll
        for (int mi = 0; mi < 2; mi++) {
            int r0 = m0 + wm * 32 + mi * 16 + g8;
#pragma unroll
            for (int ni = 0; ni < 4; ni++) {
                int n = n0 + wn * 32 + ni * 8 + 2 * t4;
                float b0v = bias[n], b1v = bias[n + 1];
#pragma unroll
                for (int rr = 0; rr < 2; rr++) {
                    int m = r0 + rr * 8;
                    float y0 = acc[mi][ni][rr * 2 + 0] + b0v;
                    float y1 = acc[mi][ni][rr * 2 + 1] + b1v;
                    *(float2*)(out + ((long)m * SEQ + t) * OUTD + n) = make_float2(y0, y1);
                    bf16 h0 = __float2bfloat16(y0), h1 = __float2bfloat16(y1);
                    hh[(long)m * ldh + n] = h0;
                    hh[(long)m * ldh + n + 1] = h1;
                    hl[(long)m * ldh + n] = __float2bfloat16(y0 - __bfloat162float(h0));
                    hl[(long)m * ldh + n + 1] = __float2bfloat16(y1 - __bfloat162float(h1));
                }
            }
        }
    }
}

// ---------------- prep: split + permute weights -------------
__global__ void prep(const float* __restrict__ z, const float* __restrict__ lin1_w,
                     const float* __restrict__ w_ih0, const float* __restrict__ w_hh0,
                     const float* __restrict__ b0,
                     const float* __restrict__ w_ih1, const float* __restrict__ w_hh1,
                     const float* __restrict__ b1,
                     const float* __restrict__ p1_w, const float* __restrict__ p2_w) {
    long stride = (long)gridDim.x * blockDim.x;
    long i0 = (long)blockIdx.x * blockDim.x + threadIdx.x;

    for (long idx = i0; idx < (long)G4 * KC1; idx += stride) {
        int n = (int)(idx / KC1), k = (int)(idx % KC1);
        int g = (n >> 3) & 3, j = (n >> 5) * 8 + (n & 7), sr = g * HID + j;
        float v = (k < OUTD) ? w_ih0[(long)sr * OUTD + k] : w_hh0[(long)sr * HID + (k - OUTD)];
        split2(v, &g_W1h[idx], &g_W1l[idx]);
    }
    for (long idx = i0; idx < (long)G4 * KC2; idx += stride) {
        int n = (int)(idx / KC2), k = (int)(idx % KC2);
        int g = (n >> 3) & 3, j = (n >> 5) * 8 + (n & 7), sr = g * HID + j;
        float v = (k < HID) ? w_ih1[(long)sr * HID + k] : w_hh1[(long)sr * HID + (k - HID)];
        split2(v, &g_W2h[idx], &g_W2l[idx]);
    }
    for (long idx = i0; idx < (long)2 * HID * LATENT; idx += stride)
        split2(lin1_w[idx], &g_WLh[idx], &g_WLl[idx]);
    for (long idx = i0; idx < (long)HID * HID; idx += stride)
        split2(p1_w[idx], &g_P1h[idx], &g_P1l[idx]);
    for (long idx = i0; idx < (long)OUTD * HID; idx += stride)
        split2(p2_w[idx], &g_P2h[idx], &g_P2l[idx]);
    for (long idx = i0; idx < (long)BATCH * LATENT; idx += stride)
        split2(z[idx], &g_Zh[idx], &g_Zl[idx]);
    for (long idx = i0; idx < G4; idx += stride) {
        int n = (int)idx;
        int g = (n >> 3) & 3, j = (n >> 5) * 8 + (n & 7);
        g_B1[n] = b0[g * HID + j];
        g_B2[n] = b1[g * HID + j];
    }
}

// ---------------- init LN+GELU over 2048, fill buffers for t=0 ----------------
__global__ void init_ln(const float* __restrict__ ln1_w, const float* __restrict__ ln1_b) {
    __shared__ float red[256];
    const int m = blockIdx.x, tid = threadIdx.x;
    const float* row = g_H0 + (long)m * 2048;

    float v[8], s = 0.f;
#pragma unroll
    for (int i = 0; i < 8; i++) { v[i] = row[tid + i * 256]; s += v[i]; }
    red[tid] = s; __syncthreads();
    for (int o = 128; o > 0; o >>= 1) { if (tid < o) red[tid] += red[tid + o]; __syncthreads(); }
    float mu = red[0] * (1.0f / 2048.0f);
    __syncthreads();
    float vs = 0.f;
#pragma unroll
    for (int i = 0; i < 8; i++) { float dd = v[i] - mu; vs += dd * dd; }
    red[tid] = vs; __syncthreads();
    for (int o = 128; o > 0; o >>= 1) { if (tid < o) red[tid] += red[tid + o]; __syncthreads(); }
    float rstd = rsqrtf(red[0] * (1.0f / 2048.0f) + 1e-5f);

#pragma unroll
    for (int i = 0; i < 8; i++) {
        int c = tid + i * 256;
        float y = geluf((v[i] - mu) * rstd * ln1_w[c] + ln1_b[c]);
        if (c < HID) {
            bf16 h = __float2bfloat16(y);
            bf16 l = __float2bfloat16(y - __bfloat162float(h));
            g_A1h[0][(long)m * KC1 + OUTD + c] = h;  g_A1l[0][(long)m * KC1 + OUTD + c] = l;
            g_A2h[0][(long)m * KC2 + HID + c] = h;   g_A2l[0][(long)m * KC2 + HID + c] = l;
        } else {
            g_C1[(long)m * HID + (c - HID)] = y;
            g_C2[(long)m * HID + (c - HID)] = y;
        }
    }
    if (tid < OUTD) {
        g_A1h[0][(long)m * KC1 + tid] = __float2bfloat16(0.f);
        g_A1l[0][(long)m * KC1 + tid] = __float2bfloat16(0.f);
    }
}

// ---------------- per-step LN+GELU -> PP pairs (no copies) ----------------
__global__ void step_ln(const float* __restrict__ pln_w, const float* __restrict__ pln_b) {
    __shared__ float red[256];
    const int m = blockIdx.x, tid = threadIdx.x;
    const float* prow = g_P + (long)m * HID;

    float v[4], s = 0.f;
#pragma unroll
    for (int i = 0; i < 4; i++) { v[i] = prow[tid + i * 256]; s += v[i]; }
    red[tid] = s; __syncthreads();
    for (int o = 128; o > 0; o >>= 1) { if (tid < o) red[tid] += red[tid + o]; __syncthreads(); }
    float mu = red[0] * (1.0f / 1024.0f);
    __syncthreads();
    float vs = 0.f;
#pragma unroll
    for (int i = 0; i < 4; i++) { float dd = v[i] - mu; vs += dd * dd; }
    red[tid] = vs; __syncthreads();
    for (int o = 128; o > 0; o >>= 1) { if (tid < o) red[tid] += red[tid + o]; __syncthreads(); }
    float rstd = rsqrtf(red[0] * (1.0f / 1024.0f) + 1e-5f);

#pragma unroll
    for (int i = 0; i < 4; i++) {
        int c = tid + i * 256;
        float y = geluf((v[i] - mu) * rstd * pln_w[c] + pln_b[c]);
        bf16 h = __float2bfloat16(y);
        g_PPh[(long)m * HID + c] = h;
        g_PPl[(long)m * HID + c] = __float2bfloat16(y - __bfloat162float(h));
    }
}

// ---------------- host ----------------
extern "C" void kernel_launch(void* const* d_in, const int* in_sizes, int n_in,
                              void* d_out, int out_size) {
    const float* z      = (const float*)d_in[0];
    const float* lin1_w = (const float*)d_in[1];
    const float* lin1_b = (const float*)d_in[2];
    const float* ln1_w  = (const float*)d_in[3];
    const float* ln1_b  = (const float*)d_in[4];
    const float* w_ih0  = (const float*)d_in[5];
    const float* w_hh0  = (const float*)d_in[6];
    const float* b0     = (const float*)d_in[7];
    const float* w_ih1  = (const float*)d_in[8];
    const float* w_hh1  = (const float*)d_in[9];
    const float* b1     = (const float*)d_in[10];
    const float* p1_w   = (const float*)d_in[11];
    const float* p1_b   = (const float*)d_in[12];
    const float* pln_w  = (const float*)d_in[13];
    const float* pln_b  = (const float*)d_in[14];
    const float* p2_w   = (const float*)d_in[15];
    const float* p2_b   = (const float*)d_in[16];
    float* out = (float*)d_out;

    bf16 *A1h[2], *A1l[2], *A2h[2], *A2l[2];
    bf16 *H2h, *H2l, *PPh, *PPl, *Zh, *Zl;
    bf16 *W1h, *W1l, *W2h, *W2l, *WLh, *WLl, *P1h, *P1l, *P2h, *P2l;
    float *P, *C1, *C2, *H0, *B1, *B2;
    {
        bf16 *t0, *t1;
        cudaGetSymbolAddress((void**)&t0, g_A1h); cudaGetSymbolAddress((void**)&t1, g_A1l);
        A1h[0] = t0; A1h[1] = t0 + (long)BATCH * KC1;
        A1l[0] = t1; A1l[1] = t1 + (long)BATCH * KC1;
        cudaGetSymbolAddress((void**)&t0, g_A2h); cudaGetSymbolAddress((void**)&t1, g_A2l);
        A2h[0] = t0; A2h[1] = t0 + (long)BATCH * KC2;
        A2l[0] = t1; A2l[1] = t1 + (long)BATCH * KC2;
    }
    cudaGetSymbolAddress((void**)&H2h, g_H2h); cudaGetSymbolAddress((void**)&H2l, g_H2l);
    cudaGetSymbolAddress((void**)&PPh, g_PPh); cudaGetSymbolAddress((void**)&PPl, g_PPl);
    cudaGetSymbolAddress((void**)&Zh, g_Zh);   cudaGetSymbolAddress((void**)&Zl, g_Zl);
    cudaGetSymbolAddress((void**)&W1h, g_W1h); cudaGetSymbolAddress((void**)&W1l, g_W1l);
    cudaGetSymbolAddress((void**)&W2h, g_W2h); cudaGetSymbolAddress((void**)&W2l, g_W2l);
    cudaGetSymbolAddress((void**)&WLh, g_WLh); cudaGetSymbolAddress((void**)&WLl, g_WLl);
    cudaGetSymbolAddress((void**)&P1h, g_P1h); cudaGetSymbolAddress((void**)&P1l, g_P1l);
    cudaGetSymbolAddress((void**)&P2h, g_P2h); cudaGetSymbolAddress((void**)&P2l, g_P2l);
    cudaGetSymbolAddress((void**)&P, g_P);
    cudaGetSymbolAddress((void**)&C1, g_C1);   cudaGetSymbolAddress((void**)&C2, g_C2);
    cudaGetSymbolAddress((void**)&H0, g_H0);
    cudaGetSymbolAddress((void**)&B1, g_B1);   cudaGetSymbolAddress((void**)&B2, g_B2);

    cudaFuncSetAttribute(mmagemm<0>, cudaFuncAttributeMaxDynamicSharedMemorySize, SMEM_BYTES);
    cudaFuncSetAttribute(mmagemm<1>, cudaFuncAttributeMaxDynamicSharedMemorySize, SMEM_BYTES);
    cudaFuncSetAttribute(mmagemm<2>, cudaFuncAttributeMaxDynamicSharedMemorySize, SMEM_BYTES);

    prep<<<2048, 256>>>(z, lin1_w, w_ih0, w_hh0, b0, w_ih1, w_hh1, b1, p1_w, p2_w);

    // init: H0 = z @ lin1_w^T + lin1_b   (M=512, N=2048, K=256)
    mmagemm<0><<<dim3(4, 32), 256, SMEM_BYTES>>>(Zh, Zl, LATENT, WLh, WLl, lin1_b,
        H0, 2 * HID, nullptr, nullptr, nullptr, 0, nullptr, nullptr, 0, 0);
    init_ln<<<BATCH, 256>>>(ln1_w, ln1_b);

    for (int tt = 0; tt < SEQ; tt++) {
        const int p = tt & 1, q = p ^ 1;
        // cell 1: gates = A1[p] @ W1^T + B1 -> h1 into A2[p][:, :HID] and A1[q][:, OUTD:]
        mmagemm<1><<<dim3(4, 64), 256, SMEM_BYTES>>>(A1h[p], A1l[p], KC1, W1h, W1l, B1,
            nullptr, 0, C1, A2h[p], A2l[p], KC2, A1h[q] + OUTD, A1l[q] + OUTD, KC1, 0);
        // cell 2: gates = A2[p] @ W2^T + B2 -> h2 into H2 and A2[q][:, HID:]
        mmagemm<1><<<dim3(4, 64), 256, SMEM_BYTES>>>(A2h[p], A2l[p], KC2, W2h, W2l, B2,
            nullptr, 0, C2, H2h, H2l, HID, A2h[q] + HID, A2l[q] + HID, KC2, 0);
        // p1: P = H2 @ p1_w^T + p1_b
        mmagemm<0><<<dim3(4, 16), 256, SMEM_BYTES>>>(H2h, H2l, HID, P1h, P1l, p1_b,
            P, HID, nullptr, nullptr, nullptr, 0, nullptr, nullptr, 0, 0);
        // LN + gelu -> PP pairs
        step_ln<<<BATCH, 256>>>(pln_w, pln_b);
        // output: y = PP @ p2_w^T + p2_b -> d_out[:, t, :] and A1[q][:, :OUTD]
        mmagemm<2><<<dim3(4, 2), 256, SMEM_BYTES>>>(PPh, PPl, HID, P2h, P2l, p2_b,
            out, 0, nullptr, A1h[q], A1l[q], KC1, nullptr, nullptr, 0, tt);
    }
}

// round 7
// speedup vs baseline: 3.5330x; 1.1616x over previous
#include <cuda_runtime.h>
#include <cuda_bf16.h>
#include <math.h>
#include <stdint.h>

#define BATCH 512
#define LATENT 256
#define HID 1024
#define OUTD 128
#define SEQ 96
#define G4 4096
#define KC1 1152
#define KC2 2048

typedef __nv_bfloat16 bf16;

// ---------------- static device scratch ----------------
__device__ bf16 g_A1h[2][BATCH * KC1], g_A1l[2][BATCH * KC1];   // [x | h1]
__device__ bf16 g_A2h[2][BATCH * KC2], g_A2l[2][BATCH * KC2];   // [h1 | h2]
__device__ bf16 g_H2h[BATCH * HID], g_H2l[BATCH * HID];
__device__ bf16 g_PPh[BATCH * HID], g_PPl[BATCH * HID];
__device__ float g_Pp[4 * BATCH * HID];      // p1 K-split partials
__device__ float g_Qp[16 * BATCH * OUTD];    // p2 K-split partials
__device__ float g_C1[BATCH * HID], g_C2[BATCH * HID];
__device__ float g_H0[BATCH * 2 * HID];
__device__ bf16 g_Zh[BATCH * LATENT], g_Zl[BATCH * LATENT];
__device__ bf16 g_W1h[G4 * KC1], g_W1l[G4 * KC1];
__device__ bf16 g_W2h[G4 * KC2], g_W2l[G4 * KC2];
__device__ bf16 g_WLh[2 * HID * LATENT], g_WLl[2 * HID * LATENT];
__device__ bf16 g_P1h[HID * HID], g_P1l[HID * HID];
__device__ bf16 g_P2h[OUTD * HID], g_P2l[OUTD * HID];
__device__ float g_B1[G4], g_B2[G4];
__device__ unsigned g_bar[1024];

// ---------------- helpers ----------------
__device__ __forceinline__ uint32_t smem_u32(const void* p) {
    uint32_t a;
    asm("{ .reg .u64 t; cvta.to.shared.u64 t, %1; cvt.u32.u64 %0, t; }" : "=r"(a) : "l"(p));
    return a;
}
__device__ __forceinline__ void cpa16(uint32_t dst, const void* src) {
    asm volatile("cp.async.cg.shared.global [%0], [%1], 16;" :: "r"(dst), "l"(src));
}
__device__ __forceinline__ void ldsm4(uint32_t* r, uint32_t a) {
    asm volatile("ldmatrix.sync.aligned.m8n8.x4.shared.b16 {%0,%1,%2,%3}, [%4];"
        : "=r"(r[0]), "=r"(r[1]), "=r"(r[2]), "=r"(r[3]) : "r"(a));
}
__device__ __forceinline__ void mma16816(float* c, const uint32_t* a, const uint32_t* b) {
    asm volatile("mma.sync.aligned.m16n8k16.row.col.f32.bf16.bf16.f32 "
        "{%0,%1,%2,%3}, {%4,%5,%6,%7}, {%8,%9}, {%0,%1,%2,%3};"
        : "+f"(c[0]), "+f"(c[1]), "+f"(c[2]), "+f"(c[3])
        : "r"(a[0]), "r"(a[1]), "r"(a[2]), "r"(a[3]), "r"(b[0]), "r"(b[1]));
}
__device__ __forceinline__ float sigf(float x) { return 1.0f / (1.0f + __expf(-x)); }
__device__ __forceinline__ float geluf(float x) {
    return 0.5f * x * (1.0f + erff(x * 0.70710678118654752f));
}
__device__ __forceinline__ void split2(float v, bf16* ph, bf16* pl) {
    bf16 h = __float2bfloat16(v);
    *ph = h;
    *pl = __float2bfloat16(v - __bfloat162float(h));
}
__device__ __forceinline__ uint32_t swz(uint32_t off) { return off ^ ((off >> 3) & 0x70); }

// grid-wide barrier: fence + atomic arrive + spin (monotonic counters, zeroed by prep)
__device__ __forceinline__ void gridbar(int id) {
    __syncthreads();
    if (threadIdx.x == 0) {
        __threadfence();
        unsigned need = gridDim.x;
        unsigned arr = atomicAdd(&g_bar[id], 1u) + 1u;
        if (arr < need) {
            volatile unsigned* ctr = g_bar + id;
            while (*ctr < need) { __nanosleep(64); }
        }
        __threadfence();
    }
    __syncthreads();
}

#define CHUNK_BYTES 49152
#define SMEM_BYTES (2 * CHUNK_BYTES + 1024)

// ---------------- GEMM tile: 128(m) x 64(n), warp 32x32, bf16x2 split ------
// MODE 0: out[m*ldo+n] = C (+bias[n] if bias)      MODE 1: LSTM epilogue, dual dest
template <int MODE>
__device__ void gemm_tile(
    uint32_t sb,
    const bf16* __restrict__ Ah, const bf16* __restrict__ Al, int lda,
    const bf16* __restrict__ Wh, const bf16* __restrict__ Wl, int ldw,
    int koff, int Klen,
    const float* __restrict__ bias,
    float* __restrict__ out, int ldo,
    float* __restrict__ cst,
    bf16* __restrict__ hh, bf16* __restrict__ hl, int ldh,
    bf16* __restrict__ hh2, bf16* __restrict__ hl2, int ldh2,
    int m0, int n0)
{
    const int tid = threadIdx.x, wid = tid >> 5, lane = tid & 31;
    const int wm = wid >> 1, wn = wid & 1;
    const int g8 = lane >> 2, t4 = lane & 3;

    float acc[2][4][4];
#pragma unroll
    for (int a = 0; a < 2; a++)
#pragma unroll
        for (int b = 0; b < 4; b++)
#pragma unroll
            for (int r = 0; r < 4; r++) acc[a][b][r] = 0.0f;

    const int nc = Klen >> 6;

#define ISSUE_LOAD(cc) do {                                                      \
    uint32_t buf = sb + ((cc) & 1) * CHUNK_BYTES;                                \
    const int kof = koff + (cc) * 64;                                            \
    _Pragma("unroll")                                                            \
    for (int i = 0; i < 4; i++) {                                                \
        int idx = tid + i * 256;                                                 \
        int r = idx >> 3, cq = idx & 7;                                          \
        uint32_t so = swz((uint32_t)(r * 128 + cq * 16));                        \
        long ka = (long)(m0 + r) * lda + kof + cq * 8;                           \
        cpa16(buf + so,         Ah + ka);                                        \
        cpa16(buf + 16384 + so, Al + ka);                                        \
    }                                                                            \
    _Pragma("unroll")                                                            \
    for (int i = 0; i < 2; i++) {                                                \
        int idx = tid + i * 256;                                                 \
        int r = idx >> 3, cq = idx & 7;                                          \
        uint32_t so = swz((uint32_t)(r * 128 + cq * 16));                        \
        long kw = (long)(n0 + r) * ldw + kof + cq * 8;                           \
        cpa16(buf + 32768 + so, Wh + kw);                                        \
        cpa16(buf + 40960 + so, Wl + kw);                                        \
    }                                                                            \
    asm volatile("cp.async.commit_group;" ::: "memory");                         \
} while (0)

    ISSUE_LOAD(0);

    for (int c = 0; c < nc; c++) {
        if (c + 1 < nc) {
            ISSUE_LOAD(c + 1);
            asm volatile("cp.async.wait_group 1;" ::: "memory");
        } else {
            asm volatile("cp.async.wait_group 0;" ::: "memory");
        }
        __syncthreads();

        uint32_t Ab = sb + (c & 1) * CHUNK_BYTES;
        uint32_t Wb = Ab + 32768;
#pragma unroll
        for (int ks = 0; ks < 4; ks++) {
            uint32_t ah[2][4], al[2][4];
#pragma unroll
            for (int mi = 0; mi < 2; mi++) {
                int r = wm * 32 + mi * 16 + (lane & 15);
                int kb = ks * 32 + (lane >> 4) * 16;
                uint32_t so = swz((uint32_t)(r * 128 + kb));
                ldsm4(ah[mi], Ab + so);
                ldsm4(al[mi], Ab + 16384 + so);
            }
            uint32_t bh[2][4], bl[2][4];
#pragma unroll
            for (int gp = 0; gp < 2; gp++) {
                int r = wn * 32 + gp * 16 + ((lane >> 4) & 1) * 8 + (lane & 7);
                int kb = ks * 32 + ((lane >> 3) & 1) * 16;
                uint32_t so = swz((uint32_t)(r * 128 + kb));
                ldsm4(bh[gp], Wb + so);
                ldsm4(bl[gp], Wb + 8192 + so);
            }
#pragma unroll
            for (int mi = 0; mi < 2; mi++)
#pragma unroll
                for (int g = 0; g < 4; g++) {
                    const uint32_t* bhf = &bh[g >> 1][(g & 1) * 2];
                    const uint32_t* blf = &bl[g >> 1][(g & 1) * 2];
                    mma16816(acc[mi][g], ah[mi], bhf);
                    mma16816(acc[mi][g], ah[mi], blf);
                    mma16816(acc[mi][g], al[mi], bhf);
                }
        }
        __syncthreads();
    }
#undef ISSUE_LOAD

    if (MODE == 0) {
#pragma unroll
        for (int mi = 0; mi < 2; mi++) {
            int r0 = m0 + wm * 32 + mi * 16 + g8;
#pragma unroll
            for (int ni = 0; ni < 4; ni++) {
                int n = n0 + wn * 32 + ni * 8 + 2 * t4;
                float b0v = bias ? bias[n] : 0.f;
                float b1v = bias ? bias[n + 1] : 0.f;
                float2 v0 = make_float2(acc[mi][ni][0] + b0v, acc[mi][ni][1] + b1v);
                float2 v1 = make_float2(acc[mi][ni][2] + b0v, acc[mi][ni][3] + b1v);
                *(float2*)(out + (long)r0 * ldo + n) = v0;
                *(float2*)(out + (long)(r0 + 8) * ldo + n) = v1;
            }
        }
    } else {
        const int nb = n0 + wn * 32;
        const int j0 = (nb >> 5) * 8 + 2 * t4;
        float bg[4][2];
#pragma unroll
        for (int g = 0; g < 4; g++) {
            bg[g][0] = bias[nb + g * 8 + 2 * t4];
            bg[g][1] = bias[nb + g * 8 + 2 * t4 + 1];
        }
#pragma unroll
        for (int mi = 0; mi < 2; mi++) {
            int r0 = m0 + wm * 32 + mi * 16 + g8;
#pragma unroll
            for (int rr = 0; rr < 2; rr++) {
                int m = r0 + rr * 8;
                const long crow = (long)m * HID;
#pragma unroll
                for (int u = 0; u < 2; u++) {
                    int j = j0 + u;
                    int reg = rr * 2 + u;
                    float xi = acc[mi][0][reg] + bg[0][u];
                    float xf = acc[mi][1][reg] + bg[1][u];
                    float xg = acc[mi][2][reg] + bg[2][u];
                    float xo = acc[mi][3][reg] + bg[3][u];
                    float cold = cst[crow + j];
                    float cn = sigf(xf) * cold + sigf(xi) * tanhf(xg);
                    float hn = sigf(xo) * tanhf(cn);
                    cst[crow + j] = cn;
                    bf16 h = __float2bfloat16(hn);
                    bf16 l = __float2bfloat16(hn - __bfloat162float(h));
                    hh[(long)m * ldh + j] = h;
                    hl[(long)m * ldh + j] = l;
                    hh2[(long)m * ldh2 + j] = h;
                    hl2[(long)m * ldh2 + j] = l;
                }
            }
        }
    }
}

// ---------------- LN helpers (2 rows per CTA) ----------------
__device__ void init_ln_rows(int bid, const float* __restrict__ ln1_w,
                             const float* __restrict__ ln1_b) {
    __shared__ float red[256];
    const int tid = threadIdx.x;
    for (int r = 0; r < 2; r++) {
        const int m = bid * 2 + r;
        const float* row = g_H0 + (long)m * 2048;
        float v[8], s = 0.f;
#pragma unroll
        for (int i = 0; i < 8; i++) { v[i] = row[tid + i * 256]; s += v[i]; }
        red[tid] = s; __syncthreads();
        for (int o = 128; o > 0; o >>= 1) { if (tid < o) red[tid] += red[tid + o]; __syncthreads(); }
        float mu = red[0] * (1.0f / 2048.0f);
        __syncthreads();
        float vs = 0.f;
#pragma unroll
        for (int i = 0; i < 8; i++) { float dd = v[i] - mu; vs += dd * dd; }
        red[tid] = vs; __syncthreads();
        for (int o = 128; o > 0; o >>= 1) { if (tid < o) red[tid] += red[tid + o]; __syncthreads(); }
        float rstd = rsqrtf(red[0] * (1.0f / 2048.0f) + 1e-5f);
        __syncthreads();
#pragma unroll
        for (int i = 0; i < 8; i++) {
            int c = tid + i * 256;
            float y = geluf((v[i] - mu) * rstd * ln1_w[c] + ln1_b[c]);
            if (c < HID) {
                bf16 h = __float2bfloat16(y);
                bf16 l = __float2bfloat16(y - __bfloat162float(h));
                g_A1h[0][(long)m * KC1 + OUTD + c] = h;  g_A1l[0][(long)m * KC1 + OUTD + c] = l;
                g_A2h[0][(long)m * KC2 + HID + c] = h;   g_A2l[0][(long)m * KC2 + HID + c] = l;
            } else {
                g_C1[(long)m * HID + (c - HID)] = y;
                g_C2[(long)m * HID + (c - HID)] = y;
            }
        }
        if (tid < OUTD) {
            g_A1h[0][(long)m * KC1 + tid] = __float2bfloat16(0.f);
            g_A1l[0][(long)m * KC1 + tid] = __float2bfloat16(0.f);
        }
    }
}

__device__ void step_ln_rows(int bid, const float* __restrict__ p1_b,
                             const float* __restrict__ pln_w, const float* __restrict__ pln_b) {
    __shared__ float red[256];
    const int tid = threadIdx.x;
    for (int r = 0; r < 2; r++) {
        const int m = bid * 2 + r;
        float v[4], s = 0.f;
#pragma unroll
        for (int i = 0; i < 4; i++) {
            int c = tid + i * 256;
            float x = p1_b[c];
#pragma unroll
            for (int ks = 0; ks < 4; ks++) x += g_Pp[ks * BATCH * HID + (long)m * HID + c];
            v[i] = x; s += x;
        }
        red[tid] = s; __syncthreads();
        for (int o = 128; o > 0; o >>= 1) { if (tid < o) red[tid] += red[tid + o]; __syncthreads(); }
        float mu = red[0] * (1.0f / 1024.0f);
        __syncthreads();
        float vs = 0.f;
#pragma unroll
        for (int i = 0; i < 4; i++) { float dd = v[i] - mu; vs += dd * dd; }
        red[tid] = vs; __syncthreads();
        for (int o = 128; o > 0; o >>= 1) { if (tid < o) red[tid] += red[tid + o]; __syncthreads(); }
        float rstd = rsqrtf(red[0] * (1.0f / 1024.0f) + 1e-5f);
        __syncthreads();
#pragma unroll
        for (int i = 0; i < 4; i++) {
            int c = tid + i * 256;
            float y = geluf((v[i] - mu) * rstd * pln_w[c] + pln_b[c]);
            split2(y, &g_PPh[(long)m * HID + c], &g_PPl[(long)m * HID + c]);
        }
    }
}

// ---------------- the persistent decoder ----------------
__global__ void __launch_bounds__(256, 2) decoder(
    const float* __restrict__ lin1_b, const float* __restrict__ ln1_w,
    const float* __restrict__ ln1_b, const float* __restrict__ p1_b,
    const float* __restrict__ pln_w, const float* __restrict__ pln_b,
    const float* __restrict__ p2_b, float* __restrict__ out)
{
    extern __shared__ char smem_raw[];
    uint32_t sb_raw = smem_u32(smem_raw);
    uint32_t sb = (sb_raw + 1023u) & ~1023u;
    const int bid = blockIdx.x;
    int barid = 0;

    // init: H0 = z @ lin1_w^T + lin1_b  (128 CTAs)
    if (bid < 128)
        gemm_tile<0>(sb, g_Zh, g_Zl, LATENT, g_WLh, g_WLl, LATENT, 0, LATENT,
                     lin1_b, g_H0, 2 * HID, nullptr, nullptr, nullptr, 0,
                     nullptr, nullptr, 0, (bid & 3) * 128, (bid >> 2) * 64);
    gridbar(barid++);
    init_ln_rows(bid, ln1_w, ln1_b);
    gridbar(barid++);

    for (int t = 0; t < SEQ; t++) {
        const int p = t & 1, q = p ^ 1;
        // cell 1 (256 CTAs): K=1152
        gemm_tile<1>(sb, g_A1h[p], g_A1l[p], KC1, g_W1h, g_W1l, KC1, 0, KC1,
                     g_B1, nullptr, 0, g_C1, g_A2h[p], g_A2l[p], KC2,
                     g_A1h[q] + OUTD, g_A1l[q] + OUTD, KC1,
                     (bid & 3) * 128, (bid >> 2) * 64);
        gridbar(barid++);
        // cell 2 (256 CTAs): K=2048
        gemm_tile<1>(sb, g_A2h[p], g_A2l[p], KC2, g_W2h, g_W2l, KC2, 0, KC2,
                     g_B2, nullptr, 0, g_C2, g_H2h, g_H2l, HID,
                     g_A2h[q] + HID, g_A2l[q] + HID, KC2,
                     (bid & 3) * 128, (bid >> 2) * 64);
        gridbar(barid++);
        // p1 K-split x4 (256 CTAs): partials
        {
            int ks = bid & 3, mt = (bid >> 2) & 3, nt = bid >> 4;
            gemm_tile<0>(sb, g_H2h, g_H2l, HID, g_P1h, g_P1l, HID, ks * 256, 256,
                         nullptr, g_Pp + ks * BATCH * HID, HID, nullptr,
                         nullptr, nullptr, 0, nullptr, nullptr, 0,
                         mt * 128, nt * 64);
        }
        gridbar(barid++);
        // sum partials + p1_b, LN + gelu -> PP pairs
        step_ln_rows(bid, p1_b, pln_w, pln_b);
        gridbar(barid++);
        // p2 K-split x16 (128 CTAs): partials
        if (bid < 128) {
            int ks = bid & 15, mt = (bid >> 4) & 3, nt = (bid >> 6) & 1;
            gemm_tile<0>(sb, g_PPh, g_PPl, HID, g_P2h, g_P2l, HID, ks * 64, 64,
                         nullptr, g_Qp + ks * BATCH * OUTD, OUTD, nullptr,
                         nullptr, nullptr, 0, nullptr, nullptr, 0,
                         mt * 128, nt * 64);
        }
        gridbar(barid++);
        // reduce partials + p2_b -> d_out[:, t, :] and next x pairs
        {
            int idx = bid * 256 + threadIdx.x;     // 0..65535
            int m = idx >> 7, n = idx & 127;
            float s = p2_b[n];
#pragma unroll
            for (int k2 = 0; k2 < 16; k2++) s += g_Qp[k2 * BATCH * OUTD + idx];
            out[((long)m * SEQ + t) * OUTD + n] = s;
            split2(s, &g_A1h[q][(long)m * KC1 + n], &g_A1l[q][(long)m * KC1 + n]);
        }
        gridbar(barid++);
    }
}

// ---------------- prep: split + permute weights, zero barriers -------------
__global__ void prep(const float* __restrict__ z, const float* __restrict__ lin1_w,
                     const float* __restrict__ w_ih0, const float* __restrict__ w_hh0,
                     const float* __restrict__ b0,
                     const float* __restrict__ w_ih1, const float* __restrict__ w_hh1,
                     const float* __restrict__ b1,
                     const float* __restrict__ p1_w, const float* __restrict__ p2_w) {
    long stride = (long)gridDim.x * blockDim.x;
    long i0 = (long)blockIdx.x * blockDim.x + threadIdx.x;

    for (long idx = i0; idx < 1024; idx += stride) g_bar[idx] = 0u;

    for (long idx = i0; idx < (long)G4 * KC1; idx += stride) {
        int n = (int)(idx / KC1), k = (int)(idx % KC1);
        int g = (n >> 3) & 3, j = (n >> 5) * 8 + (n & 7), sr = g * HID + j;
        float v = (k < OUTD) ? w_ih0[(long)sr * OUTD + k] : w_hh0[(long)sr * HID + (k - OUTD)];
        split2(v, &g_W1h[idx], &g_W1l[idx]);
    }
    for (long idx = i0; idx < (long)G4 * KC2; idx += stride) {
        int n = (int)(idx / KC2), k = (int)(idx % KC2);
        int g = (n >> 3) & 3, j = (n >> 5) * 8 + (n & 7), sr = g * HID + j;
        float v = (k < HID) ? w_ih1[(long)sr * HID + k] : w_hh1[(long)sr * HID + (k - HID)];
        split2(v, &g_W2h[idx], &g_W2l[idx]);
    }
    for (long idx = i0; idx < (long)2 * HID * LATENT; idx += stride)
        split2(lin1_w[idx], &g_WLh[idx], &g_WLl[idx]);
    for (long idx = i0; idx < (long)HID * HID; idx += stride)
        split2(p1_w[idx], &g_P1h[idx], &g_P1l[idx]);
    for (long idx = i0; idx < (long)OUTD * HID; idx += stride)
        split2(p2_w[idx], &g_P2h[idx], &g_P2l[idx]);
    for (long idx = i0; idx < (long)BATCH * LATENT; idx += stride)
        split2(z[idx], &g_Zh[idx], &g_Zl[idx]);
    for (long idx = i0; idx < G4; idx += stride) {
        int n = (int)idx;
        int g = (n >> 3) & 3, j = (n >> 5) * 8 + (n & 7);
        g_B1[n] = b0[g * HID + j];
        g_B2[n] = b1[g * HID + j];
    }
}

// ---------------- host ----------------
extern "C" void kernel_launch(void* const* d_in, const int* in_sizes, int n_in,
                              void* d_out, int out_size) {
    const float* z      = (const float*)d_in[0];
    const float* lin1_w = (const float*)d_in[1];
    const float* lin1_b = (const float*)d_in[2];
    const float* ln1_w  = (const float*)d_in[3];
    const float* ln1_b  = (const float*)d_in[4];
    const float* w_ih0  = (const float*)d_in[5];
    const float* w_hh0  = (const float*)d_in[6];
    const float* b0     = (const float*)d_in[7];
    const float* w_ih1  = (const float*)d_in[8];
    const float* w_hh1  = (const float*)d_in[9];
    const float* b1     = (const float*)d_in[10];
    const float* p1_w   = (const float*)d_in[11];
    const float* p1_b   = (const float*)d_in[12];
    const float* pln_w  = (const float*)d_in[13];
    const float* pln_b  = (const float*)d_in[14];
    const float* p2_w   = (const float*)d_in[15];
    const float* p2_b   = (const float*)d_in[16];
    float* out = (float*)d_out;

    cudaFuncSetAttribute(decoder, cudaFuncAttributeMaxDynamicSharedMemorySize, SMEM_BYTES);

    prep<<<2048, 256>>>(z, lin1_w, w_ih0, w_hh0, b0, w_ih1, w_hh1, b1, p1_w, p2_w);
    decoder<<<256, 256, SMEM_BYTES>>>(lin1_b, ln1_w, ln1_b, p1_b, pln_w, pln_b, p2_b, out);
}